// round 5
// baseline (speedup 1.0000x reference)
#include <cuda_runtime.h>
#include <cstdint>

#define NNODES 50000
#define HID 32
#define NCLS 16
#define FIN 128
#define BUCKET 128            // max supported degree per node (Poisson(32): safe)

// ---- scratch (__device__ globals; allocation-free contract) ----
__device__ __align__(16) int   g_deg[NNODES];
__device__ __align__(16) int   g_csr[NNODES * BUCKET];       // 25.6 MB
__device__ __align__(16) float g_z[(NNODES + 1) * HID];      // +1 zero row (sentinel)
__device__ __align__(16) float g_h1[NNODES * HID];

// ---------------------------------------------------------------------------
// init: zero degree counters + sentinel z-row
// ---------------------------------------------------------------------------
__global__ void k_init() {
    int i = blockIdx.x * blockDim.x + threadIdx.x;
    if (i < NNODES) g_deg[i] = 0;
    if (i < HID) g_z[NNODES * HID + i] = 0.f;
}

// ---------------------------------------------------------------------------
// fused degree-count + bucket fill, 4 edges/thread via int4
// ---------------------------------------------------------------------------
__global__ void k_fill4(const int* __restrict__ src, const int* __restrict__ dst, int E4) {
    int i = blockIdx.x * blockDim.x + threadIdx.x;
    if (i >= E4) return;
    int4 s4 = ((const int4*)src)[i];
    int4 d4 = ((const int4*)dst)[i];
    int p;
    p = atomicAdd(&g_deg[d4.x], 1); if (p < BUCKET) g_csr[(d4.x << 7) + p] = s4.x;
    p = atomicAdd(&g_deg[d4.y], 1); if (p < BUCKET) g_csr[(d4.y << 7) + p] = s4.y;
    p = atomicAdd(&g_deg[d4.z], 1); if (p < BUCKET) g_csr[(d4.z << 7) + p] = s4.z;
    p = atomicAdd(&g_deg[d4.w], 1); if (p < BUCKET) g_csr[(d4.w << 7) + p] = s4.w;
}

__global__ void k_fill_tail(const int* __restrict__ src, const int* __restrict__ dst,
                            int start, int E) {
    int i = start + blockIdx.x * blockDim.x + threadIdx.x;
    if (i >= E) return;
    int d = dst[i];
    int pos = atomicAdd(&g_deg[d], 1);
    if (pos < BUCKET) g_csr[(d << 7) + pos] = src[i];
}

// ---------------------------------------------------------------------------
// Layer-1 GEMM: z[i] = (x[i] @ W1) * rsqrt(deg+1); 64 nodes/blk, 8/warp
// ---------------------------------------------------------------------------
__global__ void k_gemm1(const float* __restrict__ x, const float* __restrict__ W) {
    __shared__ float xs[64][FIN];        // 32 KB
    __shared__ float Wst[HID][FIN + 4];  // transposed
    int tid = threadIdx.x;
    int nbase = blockIdx.x * 64;

    for (int i = tid; i < FIN * HID; i += 256) {
        int k = i >> 5, c = i & 31;
        Wst[c][k] = W[i];
    }
    const float4* x4 = (const float4*)(x + (size_t)nbase * FIN);
    float4* xs4 = (float4*)&xs[0][0];
    for (int i = tid; i < 64 * FIN / 4; i += 256) {
        int node = nbase + (i >> 5);
        xs4[i] = (node < NNODES) ? x4[i] : make_float4(0.f, 0.f, 0.f, 0.f);
    }
    __syncthreads();

    int warp = tid >> 5, lane = tid & 31;
    int n0 = warp * 8;
    float acc[8];
#pragma unroll
    for (int j = 0; j < 8; j++) acc[j] = 0.f;
#pragma unroll 2
    for (int k4 = 0; k4 < FIN / 4; k4++) {
        float4 wv = *(const float4*)&Wst[lane][k4 * 4];
#pragma unroll
        for (int j = 0; j < 8; j++) {
            float4 v = *(const float4*)&xs[n0 + j][k4 * 4];
            acc[j] = fmaf(v.x, wv.x, fmaf(v.y, wv.y, fmaf(v.z, wv.z, fmaf(v.w, wv.w, acc[j]))));
        }
    }
#pragma unroll
    for (int j = 0; j < 8; j++) {
        int node = nbase + n0 + j;
        if (node < NNODES) {
            float dn = rsqrtf((float)(__ldg(&g_deg[node]) + 1));
            g_z[node * HID + lane] = acc[j] * dn;
        }
    }
}

// ---------------------------------------------------------------------------
// Layer-2 GEMM: z[i] = (h[i] @ W2) * rsqrt(deg+1); 64 nodes/blk, 8/warp
// ---------------------------------------------------------------------------
__global__ void k_gemm2(const float* __restrict__ h, const float* __restrict__ W) {
    __shared__ float hs[64][HID];        // 8 KB
    __shared__ float Wst[HID][HID + 4];
    int tid = threadIdx.x;
    int nbase = blockIdx.x * 64;

    for (int i = tid; i < HID * HID; i += 256) {
        int k = i >> 5, c = i & 31;
        Wst[c][k] = W[i];
    }
    const float4* h4 = (const float4*)(h + (size_t)nbase * HID);
    float4* hs4 = (float4*)&hs[0][0];
    for (int i = tid; i < 64 * HID / 4; i += 256) {
        int node = nbase + (i >> 3);
        hs4[i] = (node < NNODES) ? h4[i] : make_float4(0.f, 0.f, 0.f, 0.f);
    }
    __syncthreads();

    int warp = tid >> 5, lane = tid & 31;
    int n0 = warp * 8;
    float acc[8];
#pragma unroll
    for (int j = 0; j < 8; j++) acc[j] = 0.f;
#pragma unroll
    for (int k4 = 0; k4 < HID / 4; k4++) {
        float4 wv = *(const float4*)&Wst[lane][k4 * 4];
#pragma unroll
        for (int j = 0; j < 8; j++) {
            float4 v = *(const float4*)&hs[n0 + j][k4 * 4];
            acc[j] = fmaf(v.x, wv.x, fmaf(v.y, wv.y, fmaf(v.z, wv.z, fmaf(v.w, wv.w, acc[j]))));
        }
    }
#pragma unroll
    for (int j = 0; j < 8; j++) {
        int node = nbase + n0 + j;
        if (node < NNODES) {
            float dn = rsqrtf((float)(__ldg(&g_deg[node]) + 1));
            g_z[node * HID + lane] = acc[j] * dn;
        }
    }
}

// ---------------------------------------------------------------------------
// Aggregation: warp per node; 4 edges per warp-step (8 lanes x float4 per edge),
// fp32 gathers (LDG.128), fused tanh (+ optional classifier).
// Out-of-range lanes read the sentinel zero-row (index NNODES).
// ---------------------------------------------------------------------------
template <bool CLS>
__global__ void k_agg(const float* __restrict__ b, float* __restrict__ out,
                      const float* __restrict__ Wc, const float* __restrict__ bc,
                      float* __restrict__ out_cls) {
    __shared__ float Wcs[HID * NCLS];
    __shared__ float bcs[NCLS];
    __shared__ float hrow[8][HID];
    if (CLS) {
        for (int i = threadIdx.x; i < HID * NCLS; i += 256) Wcs[i] = Wc[i];
        if (threadIdx.x < NCLS) bcs[threadIdx.x] = bc[threadIdx.x];
        __syncthreads();
    }

    int warp = threadIdx.x >> 5;
    int lane = threadIdx.x & 31;
    int n = blockIdx.x * 8 + warp;           // grid = 6250 exact
    int which = lane >> 3;                   // 0..3: edge slot within step
    int c4 = lane & 7;                       // float4 channel-group index

    const float4* z4 = (const float4*)g_z;   // 8 float4 per row
    float4 acc = make_float4(0.f, 0.f, 0.f, 0.f);
    if (which == 0)                          // self loop counted once
        acc = __ldg(&z4[n * 8 + c4]);

    int base = n << 7;
    int cnt = min(__ldg(&g_deg[n]), BUCKET);

    for (int j = 0; j < cnt; j += 32) {
        int idx = NNODES;                    // sentinel -> zero row
        if (j + lane < cnt) idx = g_csr[base + j + lane];
        int lim = min(32, ((cnt - j) + 3) & ~3);   // round up to 4
#pragma unroll 4
        for (int t = 0; t < lim; t += 4) {
            int s = __shfl_sync(0xffffffff, idx, t + which);
            float4 v = __ldg(&z4[s * 8 + c4]);
            acc.x += v.x; acc.y += v.y; acc.z += v.z; acc.w += v.w;
        }
    }

    // reduce over the 4 edge-slot groups
#pragma unroll
    for (int m = 8; m <= 16; m <<= 1) {
        acc.x += __shfl_xor_sync(0xffffffff, acc.x, m);
        acc.y += __shfl_xor_sync(0xffffffff, acc.y, m);
        acc.z += __shfl_xor_sync(0xffffffff, acc.z, m);
        acc.w += __shfl_xor_sync(0xffffffff, acc.w, m);
    }

    float dn = rsqrtf((float)(cnt + 1));
    float4 bv = __ldg(&((const float4*)b)[c4]);
    float4 hv;
    hv.x = tanhf(fmaf(acc.x, dn, bv.x));
    hv.y = tanhf(fmaf(acc.y, dn, bv.y));
    hv.z = tanhf(fmaf(acc.z, dn, bv.z));
    hv.w = tanhf(fmaf(acc.w, dn, bv.w));

    if (lane < 8)
        ((float4*)out)[n * 8 + c4] = hv;

    if (CLS) {
        if (lane < 8)
            *(float4*)&hrow[warp][c4 * 4] = hv;
        __syncwarp();
        if (lane < NCLS) {
            float a = bcs[lane];
#pragma unroll
            for (int k = 0; k < HID; k++)
                a = fmaf(hrow[warp][k], Wcs[k * NCLS + lane], a);
            out_cls[n * NCLS + lane] = a;
        }
    }
}

// ---------------------------------------------------------------------------
extern "C" void kernel_launch(void* const* d_in, const int* in_sizes, int n_in,
                              void* d_out, int out_size) {
    const float* x   = (const float*)d_in[0];
    const int*   ei  = (const int*)d_in[1];
    const float* W1  = (const float*)d_in[2];
    const float* b1  = (const float*)d_in[3];
    const float* W2  = (const float*)d_in[4];
    const float* b2  = (const float*)d_in[5];
    const float* Wc  = (const float*)d_in[6];
    const float* bc  = (const float*)d_in[7];

    const int E = in_sizes[1] / 2;
    const int* src = ei;
    const int* dst = ei + E;

    float* out_cls = (float*)d_out;                    // [N, 16]
    float* h2_out  = (float*)d_out + NNODES * NCLS;    // [N, 32]

    float* h1_p;
    cudaGetSymbolAddress((void**)&h1_p, g_h1);

    const int T = 256;
    const int E4 = E / 4;

    // bucketed CSR build
    k_init<<<(NNODES + T - 1) / T, T>>>();
    k_fill4<<<(E4 + T - 1) / T, T>>>(src, dst, E4);
    if (E % 4)
        k_fill_tail<<<1, T>>>(src, dst, E4 * 4, E);

    // layer 1
    k_gemm1<<<(NNODES + 63) / 64, T>>>(x, W1);
    k_agg<false><<<NNODES / 8, T>>>(b1, h1_p, nullptr, nullptr, nullptr);

    // layer 2 (+ fused classifier)
    k_gemm2<<<(NNODES + 63) / 64, T>>>(h1_p, W2);
    k_agg<true><<<NNODES / 8, T>>>(b2, h2_out, Wc, bc, out_cls);
}

// round 7
// speedup vs baseline: 1.0205x; 1.0205x over previous
#include <cuda_runtime.h>
#include <cstdint>

#define NNODES 50000
#define HID 32
#define NCLS 16
#define FIN 128
#define BUCKET 128            // max supported degree per node (Poisson(32): safe)

// packed dual-fp32 add (Blackwell f32x2; bit-exact vs two scalar FADDs)
#define ADDF32X2(acc, v) \
    asm("add.rn.f32x2 %0, %1, %2;" : "=l"(acc) : "l"(acc), "l"(v))

// ---- scratch (__device__ globals; allocation-free contract) ----
__device__ __align__(16) int   g_deg[NNODES];
__device__ __align__(16) int   g_csr[NNODES * BUCKET];       // 25.6 MB
__device__ __align__(16) float g_z[(NNODES + 1) * HID];      // +1 zero row (sentinel)
__device__ __align__(16) float g_h1[NNODES * HID];

// ---------------------------------------------------------------------------
__global__ void k_init() {
    int i = blockIdx.x * blockDim.x + threadIdx.x;
    if (i < NNODES) g_deg[i] = 0;
    if (i < HID) g_z[NNODES * HID + i] = 0.f;
}

// ---------------------------------------------------------------------------
// fused degree-count + bucket fill, 4 edges/thread via int4
// ---------------------------------------------------------------------------
__global__ void k_fill4(const int* __restrict__ src, const int* __restrict__ dst, int E4) {
    int i = blockIdx.x * blockDim.x + threadIdx.x;
    if (i >= E4) return;
    int4 s4 = ((const int4*)src)[i];
    int4 d4 = ((const int4*)dst)[i];
    int p;
    p = atomicAdd(&g_deg[d4.x], 1); if (p < BUCKET) g_csr[(d4.x << 7) + p] = s4.x;
    p = atomicAdd(&g_deg[d4.y], 1); if (p < BUCKET) g_csr[(d4.y << 7) + p] = s4.y;
    p = atomicAdd(&g_deg[d4.z], 1); if (p < BUCKET) g_csr[(d4.z << 7) + p] = s4.z;
    p = atomicAdd(&g_deg[d4.w], 1); if (p < BUCKET) g_csr[(d4.w << 7) + p] = s4.w;
}

__global__ void k_fill_tail(const int* __restrict__ src, const int* __restrict__ dst,
                            int start, int E) {
    int i = start + blockIdx.x * blockDim.x + threadIdx.x;
    if (i >= E) return;
    int d = dst[i];
    int pos = atomicAdd(&g_deg[d], 1);
    if (pos < BUCKET) g_csr[(d << 7) + pos] = src[i];
}

// ---------------------------------------------------------------------------
// Layer-1 GEMM: z[i] = (x[i] @ W1) * rsqrt(deg+1); 64 nodes/blk, 8/warp
// ---------------------------------------------------------------------------
__global__ void k_gemm1(const float* __restrict__ x, const float* __restrict__ W) {
    __shared__ float xs[64][FIN];
    __shared__ float Wst[HID][FIN + 4];
    int tid = threadIdx.x;
    int nbase = blockIdx.x * 64;

    for (int i = tid; i < FIN * HID; i += 256) {
        int k = i >> 5, c = i & 31;
        Wst[c][k] = W[i];
    }
    const float4* x4 = (const float4*)(x + (size_t)nbase * FIN);
    float4* xs4 = (float4*)&xs[0][0];
    for (int i = tid; i < 64 * FIN / 4; i += 256) {
        int node = nbase + (i >> 5);
        xs4[i] = (node < NNODES) ? x4[i] : make_float4(0.f, 0.f, 0.f, 0.f);
    }
    __syncthreads();

    int warp = tid >> 5, lane = tid & 31;
    int n0 = warp * 8;
    float acc[8];
#pragma unroll
    for (int j = 0; j < 8; j++) acc[j] = 0.f;
#pragma unroll 2
    for (int k4 = 0; k4 < FIN / 4; k4++) {
        float4 wv = *(const float4*)&Wst[lane][k4 * 4];
#pragma unroll
        for (int j = 0; j < 8; j++) {
            float4 v = *(const float4*)&xs[n0 + j][k4 * 4];
            acc[j] = fmaf(v.x, wv.x, fmaf(v.y, wv.y, fmaf(v.z, wv.z, fmaf(v.w, wv.w, acc[j]))));
        }
    }
#pragma unroll
    for (int j = 0; j < 8; j++) {
        int node = nbase + n0 + j;
        if (node < NNODES) {
            float dn = rsqrtf((float)(__ldg(&g_deg[node]) + 1));
            g_z[node * HID + lane] = acc[j] * dn;
        }
    }
}

// ---------------------------------------------------------------------------
// Layer-2 GEMM: z[i] = (h[i] @ W2) * rsqrt(deg+1); 64 nodes/blk, 8/warp
// ---------------------------------------------------------------------------
__global__ void k_gemm2(const float* __restrict__ h, const float* __restrict__ W) {
    __shared__ float hs[64][HID];
    __shared__ float Wst[HID][HID + 4];
    int tid = threadIdx.x;
    int nbase = blockIdx.x * 64;

    for (int i = tid; i < HID * HID; i += 256) {
        int k = i >> 5, c = i & 31;
        Wst[c][k] = W[i];
    }
    const float4* h4 = (const float4*)(h + (size_t)nbase * HID);
    float4* hs4 = (float4*)&hs[0][0];
    for (int i = tid; i < 64 * HID / 4; i += 256) {
        int node = nbase + (i >> 3);
        hs4[i] = (node < NNODES) ? h4[i] : make_float4(0.f, 0.f, 0.f, 0.f);
    }
    __syncthreads();

    int warp = tid >> 5, lane = tid & 31;
    int n0 = warp * 8;
    float acc[8];
#pragma unroll
    for (int j = 0; j < 8; j++) acc[j] = 0.f;
#pragma unroll
    for (int k4 = 0; k4 < HID / 4; k4++) {
        float4 wv = *(const float4*)&Wst[lane][k4 * 4];
#pragma unroll
        for (int j = 0; j < 8; j++) {
            float4 v = *(const float4*)&hs[n0 + j][k4 * 4];
            acc[j] = fmaf(v.x, wv.x, fmaf(v.y, wv.y, fmaf(v.z, wv.z, fmaf(v.w, wv.w, acc[j]))));
        }
    }
#pragma unroll
    for (int j = 0; j < 8; j++) {
        int node = nbase + n0 + j;
        if (node < NNODES) {
            float dn = rsqrtf((float)(__ldg(&g_deg[node]) + 1));
            g_z[node * HID + lane] = acc[j] * dn;
        }
    }
}

// ---------------------------------------------------------------------------
// Aggregation: warp per node; 4 edges per step (8 lanes x 16B per edge).
// Fast path: fixed 32-edge chunk fully unrolled -> 8 LDG.128 in flight.
// Packed f32x2 accumulation (1 warp-instr per edge in steady state).
// ---------------------------------------------------------------------------
template <bool CLS>
__global__ void __launch_bounds__(256) k_agg(
        const float* __restrict__ b, float* __restrict__ out,
        const float* __restrict__ Wc, const float* __restrict__ bc,
        float* __restrict__ out_cls) {
    __shared__ float Wcs[HID * NCLS];
    __shared__ float bcs[NCLS];
    __shared__ float hrow[8][HID];
    if (CLS) {
        for (int i = threadIdx.x; i < HID * NCLS; i += 256) Wcs[i] = Wc[i];
        if (threadIdx.x < NCLS) bcs[threadIdx.x] = bc[threadIdx.x];
        __syncthreads();
    }

    int warp = threadIdx.x >> 5;
    int lane = threadIdx.x & 31;
    int n = blockIdx.x * 8 + warp;           // grid = 6250 exact
    int which = lane >> 3;                   // 0..3: edge slot within step
    int c4 = lane & 7;                       // 16B channel-group index

    const ulonglong2* zv = (const ulonglong2*)g_z;   // 8 x 16B per row
    unsigned long long a01 = 0ull, a23 = 0ull;       // packed f32x2 accumulators
    if (which == 0) {                                 // self loop counted once
        ulonglong2 s = __ldg(&zv[n * 8 + c4]);
        a01 = s.x; a23 = s.y;
    }

    int base = n << 7;
    int cnt = min(__ldg(&g_deg[n]), BUCKET);
    int pcnt = (cnt + 7) & ~7;

    for (int j = 0; j < pcnt; j += 32) {
        int idx = NNODES;                    // sentinel -> zero row
        if (j + lane < cnt) idx = g_csr[base + j + lane];
        int lim = min(32, pcnt - j);
        if (lim == 32) {
#pragma unroll
            for (int t = 0; t < 32; t += 4) {
                int s = __shfl_sync(0xffffffff, idx, t + which);
                ulonglong2 v = __ldg(&zv[s * 8 + c4]);
                ADDF32X2(a01, v.x);
                ADDF32X2(a23, v.y);
            }
        } else {
            for (int t = 0; t < lim; t += 4) {
                int s = __shfl_sync(0xffffffff, idx, t + which);
                ulonglong2 v = __ldg(&zv[s * 8 + c4]);
                ADDF32X2(a01, v.x);
                ADDF32X2(a23, v.y);
            }
        }
    }

    // reduce over the 4 edge-slot groups (packed)
#pragma unroll
    for (int m = 8; m <= 16; m <<= 1) {
        unsigned long long t01 = __shfl_xor_sync(0xffffffff, a01, m);
        unsigned long long t23 = __shfl_xor_sync(0xffffffff, a23, m);
        ADDF32X2(a01, t01);
        ADDF32X2(a23, t23);
    }

    float ax = __uint_as_float((unsigned)(a01 & 0xffffffffull));
    float ay = __uint_as_float((unsigned)(a01 >> 32));
    float az = __uint_as_float((unsigned)(a23 & 0xffffffffull));
    float aw = __uint_as_float((unsigned)(a23 >> 32));

    float dn = rsqrtf((float)(cnt + 1));
    float4 bv = __ldg(&((const float4*)b)[c4]);
    float4 hv;
    hv.x = tanhf(fmaf(ax, dn, bv.x));
    hv.y = tanhf(fmaf(ay, dn, bv.y));
    hv.z = tanhf(fmaf(az, dn, bv.z));
    hv.w = tanhf(fmaf(aw, dn, bv.w));

    if (lane < 8)
        ((float4*)out)[n * 8 + c4] = hv;

    if (CLS) {
        if (lane < 8)
            *(float4*)&hrow[warp][c4 * 4] = hv;
        __syncwarp();
        if (lane < NCLS) {
            float a = bcs[lane];
#pragma unroll
            for (int k = 0; k < HID; k++)
                a = fmaf(hrow[warp][k], Wcs[k * NCLS + lane], a);
            out_cls[n * NCLS + lane] = a;
        }
    }
}

// ---------------------------------------------------------------------------
extern "C" void kernel_launch(void* const* d_in, const int* in_sizes, int n_in,
                              void* d_out, int out_size) {
    const float* x   = (const float*)d_in[0];
    const int*   ei  = (const int*)d_in[1];
    const float* W1  = (const float*)d_in[2];
    const float* b1  = (const float*)d_in[3];
    const float* W2  = (const float*)d_in[4];
    const float* b2  = (const float*)d_in[5];
    const float* Wc  = (const float*)d_in[6];
    const float* bc  = (const float*)d_in[7];

    const int E = in_sizes[1] / 2;
    const int* src = ei;
    const int* dst = ei + E;

    float* out_cls = (float*)d_out;                    // [N, 16]
    float* h2_out  = (float*)d_out + NNODES * NCLS;    // [N, 32]

    float* h1_p;
    cudaGetSymbolAddress((void**)&h1_p, g_h1);

    const int T = 256;
    const int E4 = E / 4;

    // bucketed CSR build
    k_init<<<(NNODES + T - 1) / T, T>>>();
    k_fill4<<<(E4 + T - 1) / T, T>>>(src, dst, E4);
    if (E % 4)
        k_fill_tail<<<1, T>>>(src, dst, E4 * 4, E);

    // layer 1
    k_gemm1<<<(NNODES + 63) / 64, T>>>(x, W1);
    k_agg<false><<<NNODES / 8, T>>>(b1, h1_p, nullptr, nullptr, nullptr);

    // layer 2 (+ fused classifier)
    k_gemm2<<<(NNODES + 63) / 64, T>>>(h1_p, W2);
    k_agg<true><<<NNODES / 8, T>>>(b2, h2_out, Wc, bc, out_cls);
}

// round 8
// speedup vs baseline: 1.0695x; 1.0480x over previous
#include <cuda_runtime.h>
#include <cstdint>

#define NNODES 50000
#define HID 32
#define NCLS 16
#define FIN 128
#define BUCKET 128            // max supported degree per node (Poisson(32): safe)

// packed dual-fp32 add (Blackwell f32x2; bit-exact vs two scalar FADDs)
#define ADDF32X2(acc, v) \
    asm("add.rn.f32x2 %0, %1, %2;" : "=l"(acc) : "l"(acc), "l"(v))

// ---- scratch (__device__ globals; allocation-free contract) ----
__device__ __align__(16) int   g_deg[NNODES];
__device__ __align__(16) int   g_csr[NNODES * BUCKET];       // 25.6 MB
__device__ __align__(16) float g_z[(NNODES + 1) * HID];      // +1 zero row (sentinel)
__device__ __align__(16) float g_h1[NNODES * HID];

// ---------------------------------------------------------------------------
__global__ void k_init() {
    int i = blockIdx.x * blockDim.x + threadIdx.x;
    if (i < NNODES) g_deg[i] = 0;
    if (i < HID) g_z[NNODES * HID + i] = 0.f;
}

// ---------------------------------------------------------------------------
// fused degree-count + bucket fill, 4 edges/thread via int4
// ---------------------------------------------------------------------------
__global__ void k_fill4(const int* __restrict__ src, const int* __restrict__ dst, int E4) {
    int i = blockIdx.x * blockDim.x + threadIdx.x;
    if (i >= E4) return;
    int4 s4 = ((const int4*)src)[i];
    int4 d4 = ((const int4*)dst)[i];
    int p;
    p = atomicAdd(&g_deg[d4.x], 1); if (p < BUCKET) g_csr[(d4.x << 7) + p] = s4.x;
    p = atomicAdd(&g_deg[d4.y], 1); if (p < BUCKET) g_csr[(d4.y << 7) + p] = s4.y;
    p = atomicAdd(&g_deg[d4.z], 1); if (p < BUCKET) g_csr[(d4.z << 7) + p] = s4.z;
    p = atomicAdd(&g_deg[d4.w], 1); if (p < BUCKET) g_csr[(d4.w << 7) + p] = s4.w;
}

__global__ void k_fill_tail(const int* __restrict__ src, const int* __restrict__ dst,
                            int start, int E) {
    int i = start + blockIdx.x * blockDim.x + threadIdx.x;
    if (i >= E) return;
    int d = dst[i];
    int pos = atomicAdd(&g_deg[d], 1);
    if (pos < BUCKET) g_csr[(d << 7) + pos] = src[i];
}

// ---------------------------------------------------------------------------
// Layer-1 GEMM: z[i] = (x[i] @ W1) * rsqrt(deg+1); 64 nodes/blk, 8/warp
// ---------------------------------------------------------------------------
__global__ void k_gemm1(const float* __restrict__ x, const float* __restrict__ W) {
    __shared__ float xs[64][FIN];
    __shared__ float Wst[HID][FIN + 4];
    int tid = threadIdx.x;
    int nbase = blockIdx.x * 64;

    for (int i = tid; i < FIN * HID; i += 256) {
        int k = i >> 5, c = i & 31;
        Wst[c][k] = W[i];
    }
    const float4* x4 = (const float4*)(x + (size_t)nbase * FIN);
    float4* xs4 = (float4*)&xs[0][0];
    for (int i = tid; i < 64 * FIN / 4; i += 256) {
        int node = nbase + (i >> 5);
        xs4[i] = (node < NNODES) ? x4[i] : make_float4(0.f, 0.f, 0.f, 0.f);
    }
    __syncthreads();

    int warp = tid >> 5, lane = tid & 31;
    int n0 = warp * 8;
    float acc[8];
#pragma unroll
    for (int j = 0; j < 8; j++) acc[j] = 0.f;
#pragma unroll 2
    for (int k4 = 0; k4 < FIN / 4; k4++) {
        float4 wv = *(const float4*)&Wst[lane][k4 * 4];
#pragma unroll
        for (int j = 0; j < 8; j++) {
            float4 v = *(const float4*)&xs[n0 + j][k4 * 4];
            acc[j] = fmaf(v.x, wv.x, fmaf(v.y, wv.y, fmaf(v.z, wv.z, fmaf(v.w, wv.w, acc[j]))));
        }
    }
#pragma unroll
    for (int j = 0; j < 8; j++) {
        int node = nbase + n0 + j;
        if (node < NNODES) {
            float dn = rsqrtf((float)(__ldg(&g_deg[node]) + 1));
            g_z[node * HID + lane] = acc[j] * dn;
        }
    }
}

// ---------------------------------------------------------------------------
// Layer-2 GEMM: z[i] = (h[i] @ W2) * rsqrt(deg+1); 64 nodes/blk, 8/warp
// ---------------------------------------------------------------------------
__global__ void k_gemm2(const float* __restrict__ h, const float* __restrict__ W) {
    __shared__ float hs[64][HID];
    __shared__ float Wst[HID][HID + 4];
    int tid = threadIdx.x;
    int nbase = blockIdx.x * 64;

    for (int i = tid; i < HID * HID; i += 256) {
        int k = i >> 5, c = i & 31;
        Wst[c][k] = W[i];
    }
    const float4* h4 = (const float4*)(h + (size_t)nbase * HID);
    float4* hs4 = (float4*)&hs[0][0];
    for (int i = tid; i < 64 * HID / 4; i += 256) {
        int node = nbase + (i >> 3);
        hs4[i] = (node < NNODES) ? h4[i] : make_float4(0.f, 0.f, 0.f, 0.f);
    }
    __syncthreads();

    int warp = tid >> 5, lane = tid & 31;
    int n0 = warp * 8;
    float acc[8];
#pragma unroll
    for (int j = 0; j < 8; j++) acc[j] = 0.f;
#pragma unroll
    for (int k4 = 0; k4 < HID / 4; k4++) {
        float4 wv = *(const float4*)&Wst[lane][k4 * 4];
#pragma unroll
        for (int j = 0; j < 8; j++) {
            float4 v = *(const float4*)&hs[n0 + j][k4 * 4];
            acc[j] = fmaf(v.x, wv.x, fmaf(v.y, wv.y, fmaf(v.z, wv.z, fmaf(v.w, wv.w, acc[j]))));
        }
    }
#pragma unroll
    for (int j = 0; j < 8; j++) {
        int node = nbase + n0 + j;
        if (node < NNODES) {
            float dn = rsqrtf((float)(__ldg(&g_deg[node]) + 1));
            g_z[node * HID + lane] = acc[j] * dn;
        }
    }
}

// ---------------------------------------------------------------------------
// Aggregation: warp per NODE PAIR; per node 4 edges/step (8 lanes x 16B).
// Interleaved dependency chains for the two nodes -> MLP 16 per warp.
// Packed f32x2 accumulation; fused tanh (+ optional classifier).
// ---------------------------------------------------------------------------
template <bool CLS>
__global__ void __launch_bounds__(256) k_agg(
        const float* __restrict__ b, float* __restrict__ out,
        const float* __restrict__ Wc, const float* __restrict__ bc,
        float* __restrict__ out_cls) {
    __shared__ float Wcs[HID * NCLS];
    __shared__ float bcs[NCLS];
    __shared__ float hrow[8][2][HID];
    if (CLS) {
        for (int i = threadIdx.x; i < HID * NCLS; i += 256) Wcs[i] = Wc[i];
        if (threadIdx.x < NCLS) bcs[threadIdx.x] = bc[threadIdx.x];
        __syncthreads();
    }

    int warp = threadIdx.x >> 5;
    int lane = threadIdx.x & 31;
    int n0 = (blockIdx.x * 8 + warp) * 2;    // grid = 3125 exact
    int n1 = n0 + 1;
    int which = lane >> 3;                   // 0..3: edge slot within step
    int c4 = lane & 7;                       // 16B channel-group index

    const ulonglong2* zv = (const ulonglong2*)g_z;   // 8 x 16B per row
    unsigned long long a01_0 = 0ull, a23_0 = 0ull;   // node0 packed accumulators
    unsigned long long a01_1 = 0ull, a23_1 = 0ull;   // node1
    if (which == 0) {                                 // self loops counted once
        ulonglong2 s0 = __ldg(&zv[n0 * 8 + c4]);
        ulonglong2 s1 = __ldg(&zv[n1 * 8 + c4]);
        a01_0 = s0.x; a23_0 = s0.y;
        a01_1 = s1.x; a23_1 = s1.y;
    }

    int base0 = n0 << 7, base1 = n1 << 7;
    int cnt0 = min(__ldg(&g_deg[n0]), BUCKET);
    int cnt1 = min(__ldg(&g_deg[n1]), BUCKET);
    int pmax = (max(cnt0, cnt1) + 7) & ~7;

    for (int j = 0; j < pmax; j += 32) {
        int idx0 = NNODES, idx1 = NNODES;    // sentinel -> zero row
        if (j + lane < cnt0) idx0 = g_csr[base0 + j + lane];
        if (j + lane < cnt1) idx1 = g_csr[base1 + j + lane];
        int lim = min(32, pmax - j);
        if (lim == 32) {
#pragma unroll
            for (int t = 0; t < 32; t += 4) {
                int s0 = __shfl_sync(0xffffffff, idx0, t + which);
                int s1 = __shfl_sync(0xffffffff, idx1, t + which);
                ulonglong2 v0 = __ldg(&zv[s0 * 8 + c4]);
                ulonglong2 v1 = __ldg(&zv[s1 * 8 + c4]);
                ADDF32X2(a01_0, v0.x);
                ADDF32X2(a23_0, v0.y);
                ADDF32X2(a01_1, v1.x);
                ADDF32X2(a23_1, v1.y);
            }
        } else {
            for (int t = 0; t < lim; t += 4) {
                int s0 = __shfl_sync(0xffffffff, idx0, t + which);
                int s1 = __shfl_sync(0xffffffff, idx1, t + which);
                ulonglong2 v0 = __ldg(&zv[s0 * 8 + c4]);
                ulonglong2 v1 = __ldg(&zv[s1 * 8 + c4]);
                ADDF32X2(a01_0, v0.x);
                ADDF32X2(a23_0, v0.y);
                ADDF32X2(a01_1, v1.x);
                ADDF32X2(a23_1, v1.y);
            }
        }
    }

    // reduce over the 4 edge-slot groups (packed)
#pragma unroll
    for (int m = 8; m <= 16; m <<= 1) {
        unsigned long long t;
        t = __shfl_xor_sync(0xffffffff, a01_0, m); ADDF32X2(a01_0, t);
        t = __shfl_xor_sync(0xffffffff, a23_0, m); ADDF32X2(a23_0, t);
        t = __shfl_xor_sync(0xffffffff, a01_1, m); ADDF32X2(a01_1, t);
        t = __shfl_xor_sync(0xffffffff, a23_1, m); ADDF32X2(a23_1, t);
    }

    // lanes 0-7 finish node0, lanes 8-15 finish node1
    bool second = (lane >= 8);
    unsigned long long s01 = second ? a01_1 : a01_0;
    unsigned long long s23 = second ? a23_1 : a23_0;
    int node = second ? n1 : n0;
    int cntx = second ? cnt1 : cnt0;

    float ax = __uint_as_float((unsigned)(s01 & 0xffffffffull));
    float ay = __uint_as_float((unsigned)(s01 >> 32));
    float az = __uint_as_float((unsigned)(s23 & 0xffffffffull));
    float aw = __uint_as_float((unsigned)(s23 >> 32));

    float dn = rsqrtf((float)(cntx + 1));
    float4 bv = __ldg(&((const float4*)b)[c4]);
    float4 hv;
    hv.x = tanhf(fmaf(ax, dn, bv.x));
    hv.y = tanhf(fmaf(ay, dn, bv.y));
    hv.z = tanhf(fmaf(az, dn, bv.z));
    hv.w = tanhf(fmaf(aw, dn, bv.w));

    if (lane < 16)
        ((float4*)out)[node * 8 + c4] = hv;

    if (CLS) {
        if (lane < 16)
            *(float4*)&hrow[warp][lane >> 3][c4 * 4] = hv;
        __syncwarp();
        // 32 lanes = 2 nodes x 16 classes
        int nn = lane >> 4, c = lane & 15;
        float a = bcs[c];
#pragma unroll
        for (int k = 0; k < HID; k++)
            a = fmaf(hrow[warp][nn][k], Wcs[k * NCLS + c], a);
        out_cls[(n0 + nn) * NCLS + c] = a;
    }
}

// ---------------------------------------------------------------------------
extern "C" void kernel_launch(void* const* d_in, const int* in_sizes, int n_in,
                              void* d_out, int out_size) {
    const float* x   = (const float*)d_in[0];
    const int*   ei  = (const int*)d_in[1];
    const float* W1  = (const float*)d_in[2];
    const float* b1  = (const float*)d_in[3];
    const float* W2  = (const float*)d_in[4];
    const float* b2  = (const float*)d_in[5];
    const float* Wc  = (const float*)d_in[6];
    const float* bc  = (const float*)d_in[7];

    const int E = in_sizes[1] / 2;
    const int* src = ei;
    const int* dst = ei + E;

    float* out_cls = (float*)d_out;                    // [N, 16]
    float* h2_out  = (float*)d_out + NNODES * NCLS;    // [N, 32]

    float* h1_p;
    cudaGetSymbolAddress((void**)&h1_p, g_h1);

    const int T = 256;
    const int E4 = E / 4;

    // bucketed CSR build
    k_init<<<(NNODES + T - 1) / T, T>>>();
    k_fill4<<<(E4 + T - 1) / T, T>>>(src, dst, E4);
    if (E % 4)
        k_fill_tail<<<1, T>>>(src, dst, E4 * 4, E);

    // layer 1
    k_gemm1<<<(NNODES + 63) / 64, T>>>(x, W1);
    k_agg<false><<<NNODES / 16, T>>>(b1, h1_p, nullptr, nullptr, nullptr);

    // layer 2 (+ fused classifier)
    k_gemm2<<<(NNODES + 63) / 64, T>>>(h1_p, W2);
    k_agg<true><<<NNODES / 16, T>>>(b2, h2_out, Wc, bc, out_cls);
}